// round 3
// baseline (speedup 1.0000x reference)
#include <cuda_runtime.h>
#include <cstdint>
#include <cstddef>

#define TT   1024
#define BB   32
#define DIN  512
#define HH   768
#define G4   3072
#define NBLK 128

// ---------------- static device scratch (allocation-free rule) ----------------
// zx[d][t][gcol][b] : precomputed x @ W_x + bias, gate-column major, batch contiguous
__device__ float    g_zx[(size_t)2 * TT * G4 * BB];     // 805 MB
// hbuf[d][t][n][b]  : full hidden-state history (doubles as recurrent input & output staging)
__device__ float    g_hbuf[(size_t)2 * TT * HH * BB];   // 201 MB
// c[d][n][b]
__device__ float    g_c[2 * HH * BB];
__device__ unsigned g_bar_count = 0;
__device__ unsigned g_bar_gen   = 0;

// ---------------- helpers ----------------
__device__ __forceinline__ float sigf(float x) { return 1.0f / (1.0f + __expf(-x)); }

__device__ __forceinline__ unsigned long long dup2(float w) {
    unsigned long long r;
    asm("mov.b64 %0, {%1, %1};" : "=l"(r) : "f"(w));
    return r;
}
__device__ __forceinline__ void fma2(unsigned long long& d, unsigned long long a, unsigned long long w) {
    asm("fma.rn.f32x2 %0, %1, %2, %0;" : "+l"(d) : "l"(a), "l"(w));
}
__device__ __forceinline__ float2 unpack2(unsigned long long v) {
    float2 r;
    asm("mov.b64 {%0, %1}, %2;" : "=f"(r.x), "=f"(r.y) : "l"(v));
    return r;
}

// ---------------- kernel 1: input projection  zx = x @ W[:512,:] + b ----------------
// grid (48, 256, 2): x = 64-col tile, y = 128-row tile (rows = t*32+b), z = direction
__global__ __launch_bounds__(256, 2) void zx_kernel(
    const float* __restrict__ x,
    const float* __restrict__ W0, const float* __restrict__ W1,
    const float* __restrict__ b0p, const float* __restrict__ b1p)
{
    const int d = blockIdx.z;
    const float* __restrict__ W    = d ? W1 : W0;
    const float* __restrict__ bias = d ? b1p : b0p;
    const int cb  = blockIdx.x * 64;
    const int r0  = blockIdx.y * 128;
    const int tid = threadIdx.x;
    const int tm  = tid & 15;   // 16 m-groups of 8 rows
    const int tn  = tid >> 4;   // 16 n-groups of 4 cols

    __shared__ float As[16][128];
    __shared__ float Ws[16][64];

    unsigned long long acc[4][4];
#pragma unroll
    for (int i = 0; i < 4; i++)
#pragma unroll
        for (int j = 0; j < 4; j++) acc[i][j] = 0ULL;

    // A-staging geometry: thread loads 2 float4 of row a_r, k-offsets a_kq / a_kq+4
    const int a_r  = tid >> 1;                 // 0..127 (relative row)
    const int a_kq = (tid & 1) * 8;            // 0 or 8
    const int t_a  = (r0 + a_r) >> 5;
    const int b_a  = (r0 + a_r) & 31;
    const float* __restrict__ xrow = x + ((size_t)b_a * TT + t_a) * DIN;

    // W-staging geometry: thread loads 1 float4
    const int w_kk = tid >> 4;                 // 0..15
    const int w_c  = (tid & 15) * 4;           // 0..60

    float4 a0r = *(const float4*)(xrow + a_kq);
    float4 a1r = *(const float4*)(xrow + a_kq + 4);
    float4 wr  = *(const float4*)(W + (size_t)w_kk * G4 + cb + w_c);

    for (int k0 = 0; k0 < DIN; k0 += 16) {
        As[a_kq + 0][a_r] = a0r.x;  As[a_kq + 1][a_r] = a0r.y;
        As[a_kq + 2][a_r] = a0r.z;  As[a_kq + 3][a_r] = a0r.w;
        As[a_kq + 4][a_r] = a1r.x;  As[a_kq + 5][a_r] = a1r.y;
        As[a_kq + 6][a_r] = a1r.z;  As[a_kq + 7][a_r] = a1r.w;
        *(float4*)&Ws[w_kk][w_c] = wr;
        __syncthreads();

        float4 a0n, a1n, wn;
        if (k0 + 16 < DIN) {  // prefetch next chunk into registers
            a0n = *(const float4*)(xrow + k0 + 16 + a_kq);
            a1n = *(const float4*)(xrow + k0 + 16 + a_kq + 4);
            wn  = *(const float4*)(W + (size_t)(k0 + 16 + w_kk) * G4 + cb + w_c);
        }

#pragma unroll
        for (int kk = 0; kk < 16; kk++) {
            ulonglong2 aA = *(const ulonglong2*)&As[kk][tm * 8];
            ulonglong2 aB = *(const ulonglong2*)&As[kk][tm * 8 + 4];
            float4 w = *(const float4*)&Ws[kk][tn * 4];
            unsigned long long wd0 = dup2(w.x), wd1 = dup2(w.y), wd2 = dup2(w.z), wd3 = dup2(w.w);
            unsigned long long ap[4] = { aA.x, aA.y, aB.x, aB.y };
#pragma unroll
            for (int mi = 0; mi < 4; mi++) {
                fma2(acc[mi][0], ap[mi], wd0);
                fma2(acc[mi][1], ap[mi], wd1);
                fma2(acc[mi][2], ap[mi], wd2);
                fma2(acc[mi][3], ap[mi], wd3);
            }
        }
        __syncthreads();
        a0r = a0n; a1r = a1n; wr = wn;
    }

    // epilogue: add bias, write zx[d][t][col][b] (batch-pairs contiguous)
    const int t_out  = (r0 + tm * 8) >> 5;   // all 8 rows of this thread share t
    const int b_base = (r0 + tm * 8) & 31;   // 0,8,16,24
#pragma unroll
    for (int ni = 0; ni < 4; ni++) {
        const int col = cb + tn * 4 + ni;
        const float bv = bias[col];
        const size_t base = (((size_t)(d * TT + t_out)) * G4 + col) * BB + b_base;
#pragma unroll
        for (int mi = 0; mi < 4; mi++) {
            float2 v = unpack2(acc[mi][ni]);
            v.x += bv; v.y += bv;
            *(float2*)(g_zx + base + mi * 2) = v;
        }
    }
}

// ---------------- kernel 2: persistent recurrent kernel ----------------
// 128 blocks x 128 threads. Block -> (dir, 12 hidden units). One grid barrier per step.
__global__ __launch_bounds__(128, 1) void rec_kernel(
    const float* __restrict__ W0, const float* __restrict__ W1,
    const float* __restrict__ p0, const float* __restrict__ p1)
{
    const int blk = blockIdx.x;
    const int d   = blk >> 6;             // 0 = fw, 1 = bw
    const int u0  = (blk & 63) * 12;      // hidden-unit base
    const float* __restrict__ W    = d ? W1 : W0;
    const float* __restrict__ peep = d ? p1 : p0;
    const float* __restrict__ Wh   = W + (size_t)DIN * G4;  // recurrent rows

    const int tid  = threadIdx.x;
    const int bg   = tid & 7;             // 8 batch-groups of 4
    const int cg   = tid >> 3;            // 16 col-groups of 3
    const int b0   = bg * 4;
    const int gate = cg >> 2;             // 0..3 (i,j,f,o)
    const int uu   = (cg & 3) * 3;        // unit offset within the 12
    const int c0   = cg * 3;              // local column base (0..45)

    // staging geometry
    const int wk   = tid >> 2;            // W: k within chunk (0..31)
    const int wrun = tid & 3;             // W: gate run
    const int ak   = tid >> 2;            // A: k within chunk
    const int ab   = (tid & 3) * 8;       // A: batch offset

    __shared__ float As[32][32];          // h_prev chunk [k][b]
    __shared__ float Ws[32][48];          // weight chunk [k][local col]
    __shared__ float Zs[48][32];          // gate pre-activations

    for (int s = 0; s < TT; s++) {
        const int t = d ? (TT - 1 - s) : s;

        // init accumulators from zx (batch pairs are contiguous float2)
        unsigned long long acc[3][2];
        {
            const size_t zb = ((size_t)(d * TT + t) * G4 + gate * HH + u0 + uu) * BB + b0;
#pragma unroll
            for (int ci = 0; ci < 3; ci++) {
                acc[ci][0] = *(const unsigned long long*)(g_zx + zb + (size_t)ci * BB);
                acc[ci][1] = *(const unsigned long long*)(g_zx + zb + (size_t)ci * BB + 2);
            }
        }

        if (s > 0) {
            const int tprev = d ? (t + 1) : (t - 1);
            const float* __restrict__ hp = g_hbuf + (size_t)(d * TT + tprev) * HH * BB;

            float4 ar0 = *(const float4*)(hp + ak * BB + ab);
            float4 ar1 = *(const float4*)(hp + ak * BB + ab + 4);
            const float* wb0 = Wh + (size_t)wk * G4 + wrun * HH + u0;
            float4 w0 = *(const float4*)(wb0);
            float4 w1 = *(const float4*)(wb0 + 4);
            float4 w2 = *(const float4*)(wb0 + 8);

            for (int k0 = 0; k0 < HH; k0 += 32) {
                *(float4*)&As[ak][ab]     = ar0;
                *(float4*)&As[ak][ab + 4] = ar1;
                *(float4*)&Ws[wk][wrun * 12]     = w0;
                *(float4*)&Ws[wk][wrun * 12 + 4] = w1;
                *(float4*)&Ws[wk][wrun * 12 + 8] = w2;
                __syncthreads();

                if (k0 + 32 < HH) {  // register prefetch of next chunk
                    const float* hpn = hp + (size_t)(k0 + 32) * BB;
                    ar0 = *(const float4*)(hpn + ak * BB + ab);
                    ar1 = *(const float4*)(hpn + ak * BB + ab + 4);
                    const float* wbn = Wh + (size_t)(k0 + 32 + wk) * G4 + wrun * HH + u0;
                    w0 = *(const float4*)(wbn);
                    w1 = *(const float4*)(wbn + 4);
                    w2 = *(const float4*)(wbn + 8);
                }

#pragma unroll
                for (int kk = 0; kk < 32; kk++) {
                    ulonglong2 ap = *(const ulonglong2*)&As[kk][b0];
                    unsigned long long wd0 = dup2(Ws[kk][c0 + 0]);
                    unsigned long long wd1 = dup2(Ws[kk][c0 + 1]);
                    unsigned long long wd2 = dup2(Ws[kk][c0 + 2]);
                    fma2(acc[0][0], ap.x, wd0); fma2(acc[0][1], ap.y, wd0);
                    fma2(acc[1][0], ap.x, wd1); fma2(acc[1][1], ap.y, wd1);
                    fma2(acc[2][0], ap.x, wd2); fma2(acc[2][1], ap.y, wd2);
                }
                __syncthreads();
            }
        }

        // park pre-activations in smem so any thread can do the per-unit nonlinearity
#pragma unroll
        for (int ci = 0; ci < 3; ci++) {
            *(float2*)&Zs[c0 + ci][b0]     = unpack2(acc[ci][0]);
            *(float2*)&Zs[c0 + ci][b0 + 2] = unpack2(acc[ci][1]);
        }
        __syncthreads();

        // elementwise LSTM update: 12 units * 32 batch = 384 tasks, 3 per thread
#pragma unroll
        for (int e = 0; e < 3; e++) {
            const int task = tid * 3 + e;
            const int u = task >> 5;
            const int b = task & 31;
            const int n = u0 + u;
            const float zi = Zs[u][b];
            const float zj = Zs[12 + u][b];
            const float zf = Zs[24 + u][b];
            const float zo = Zs[36 + u][b];
            const int cidx = (d * HH + n) * BB + b;
            const float cp = (s > 0) ? g_c[cidx] : 0.0f;
            const float ig = sigf(zi + peep[n] * cp);
            const float fg = sigf(zf + 1.0f + peep[HH + n] * cp);
            const float cn = fg * cp + ig * tanhf(zj);
            const float og = sigf(zo + peep[2 * HH + n] * cn);
            const float hv = og * tanhf(cn);
            g_c[cidx] = cn;
            g_hbuf[((size_t)(d * TT + t) * HH + n) * BB + b] = hv;
        }

        // ---- device-wide sense-reversing barrier (all 128 blocks co-resident) ----
        __syncthreads();
        if (tid == 0) {
            __threadfence();
            const unsigned my = *(volatile unsigned*)&g_bar_gen;
            if (atomicAdd(&g_bar_count, 1u) == NBLK - 1) {
                atomicExch(&g_bar_count, 0u);
                __threadfence();
                atomicAdd(&g_bar_gen, 1u);
            } else {
                while (*(volatile unsigned*)&g_bar_gen == my) { }
            }
            __threadfence();
        }
        __syncthreads();
    }
}

// ---------------- kernel 3: transpose hbuf[d][t][n][b] -> out[b][t][d*H+n] ----------------
__global__ __launch_bounds__(256) void out_kernel(float* __restrict__ out)
{
    const int d  = blockIdx.z;
    const int t  = blockIdx.y;
    const int n0 = blockIdx.x * 32;
    const int tid = threadIdx.x;

    __shared__ float tile[32][33];

    const float* __restrict__ src = g_hbuf + ((size_t)(d * TT + t) * HH + n0) * BB;
#pragma unroll
    for (int q = 0; q < 4; q++) {
        const int lin = tid + q * 256;
        tile[lin >> 5][lin & 31] = src[lin];
    }
    __syncthreads();

    const int b  = tid >> 3;
    const int nq = (tid & 7) * 4;
    float4 v;
    v.x = tile[nq + 0][b];
    v.y = tile[nq + 1][b];
    v.z = tile[nq + 2][b];
    v.w = tile[nq + 3][b];
    *(float4*)(out + ((size_t)b * TT + t) * (2 * HH) + d * HH + n0 + nq) = v;
}

// ---------------- launch ----------------
extern "C" void kernel_launch(void* const* d_in, const int* in_sizes, int n_in,
                              void* d_out, int out_size)
{
    (void)in_sizes; (void)n_in; (void)out_size;
    const float* x  = (const float*)d_in[0];
    const float* Wf = (const float*)d_in[1];
    const float* bf = (const float*)d_in[2];
    const float* pf = (const float*)d_in[3];
    const float* Wb = (const float*)d_in[4];
    const float* bb = (const float*)d_in[5];
    const float* pb = (const float*)d_in[6];
    float* out = (float*)d_out;

    zx_kernel<<<dim3(48, 256, 2), 256>>>(x, Wf, Wb, bf, bb);
    rec_kernel<<<NBLK, 128>>>(Wf, Wb, pf, pb);
    out_kernel<<<dim3(24, TT, 2), 256>>>(out);
}

// round 10
// speedup vs baseline: 1.9468x; 1.9468x over previous
#include <cuda_runtime.h>
#include <cstdint>
#include <cstddef>

#define TT   1024
#define BB   32
#define DIN  512
#define HH   768
#define G4   3072
#define NBLK 128
#define RT   256   // rec threads

// ---------------- static device scratch ----------------
__device__ float    g_zx[(size_t)2 * TT * G4 * BB];     // zx[d][t][gcol][b]
__device__ float    g_hbuf[(size_t)2 * TT * HH * BB];   // h[d][t][n][b]
__device__ unsigned g_bar_count = 0;
__device__ unsigned g_bar_gen   = 0;

// ---------------- helpers ----------------
__device__ __forceinline__ float sigf(float x) {
    return __fdividef(1.0f, 1.0f + __expf(-x));
}
__device__ __forceinline__ float tanhfast(float x) {
    return __fdividef(2.0f, 1.0f + __expf(-2.0f * x)) - 1.0f;
}
__device__ __forceinline__ unsigned long long dup2(float w) {
    unsigned long long r;
    asm("mov.b64 %0, {%1, %1};" : "=l"(r) : "f"(w));
    return r;
}
__device__ __forceinline__ void fma2(unsigned long long& d, unsigned long long a, unsigned long long w) {
    asm("fma.rn.f32x2 %0, %1, %2, %0;" : "+l"(d) : "l"(a), "l"(w));
}
__device__ __forceinline__ float2 unpack2(unsigned long long v) {
    float2 r;
    asm("mov.b64 {%0, %1}, %2;" : "=f"(r.x), "=f"(r.y) : "l"(v));
    return r;
}
__device__ __forceinline__ unsigned long long pack2(float x, float y) {
    unsigned long long r;
    asm("mov.b64 %0, {%1, %2};" : "=l"(r) : "f"(x), "f"(y));
    return r;
}

// ---------------- kernel 1: input projection ----------------
__global__ __launch_bounds__(256, 2) void zx_kernel(
    const float* __restrict__ x,
    const float* __restrict__ W0, const float* __restrict__ W1,
    const float* __restrict__ b0p, const float* __restrict__ b1p)
{
    const int d = blockIdx.z;
    const float* __restrict__ W    = d ? W1 : W0;
    const float* __restrict__ bias = d ? b1p : b0p;
    const int cb  = blockIdx.x * 64;
    const int r0  = blockIdx.y * 128;
    const int tid = threadIdx.x;
    const int tm  = tid & 15;
    const int tn  = tid >> 4;

    __shared__ float As[16][128];
    __shared__ float Ws[16][64];

    unsigned long long acc[4][4];
#pragma unroll
    for (int i = 0; i < 4; i++)
#pragma unroll
        for (int j = 0; j < 4; j++) acc[i][j] = 0ULL;

    const int a_r  = tid >> 1;
    const int a_kq = (tid & 1) * 8;
    const int t_a  = (r0 + a_r) >> 5;
    const int b_a  = (r0 + a_r) & 31;
    const float* __restrict__ xrow = x + ((size_t)b_a * TT + t_a) * DIN;

    const int w_kk = tid >> 4;
    const int w_c  = (tid & 15) * 4;

    float4 a0r = *(const float4*)(xrow + a_kq);
    float4 a1r = *(const float4*)(xrow + a_kq + 4);
    float4 wr  = *(const float4*)(W + (size_t)w_kk * G4 + cb + w_c);

    for (int k0 = 0; k0 < DIN; k0 += 16) {
        As[a_kq + 0][a_r] = a0r.x;  As[a_kq + 1][a_r] = a0r.y;
        As[a_kq + 2][a_r] = a0r.z;  As[a_kq + 3][a_r] = a0r.w;
        As[a_kq + 4][a_r] = a1r.x;  As[a_kq + 5][a_r] = a1r.y;
        As[a_kq + 6][a_r] = a1r.z;  As[a_kq + 7][a_r] = a1r.w;
        *(float4*)&Ws[w_kk][w_c] = wr;
        __syncthreads();

        float4 a0n, a1n, wn;
        if (k0 + 16 < DIN) {
            a0n = *(const float4*)(xrow + k0 + 16 + a_kq);
            a1n = *(const float4*)(xrow + k0 + 16 + a_kq + 4);
            wn  = *(const float4*)(W + (size_t)(k0 + 16 + w_kk) * G4 + cb + w_c);
        }

#pragma unroll
        for (int kk = 0; kk < 16; kk++) {
            // conflict-free: two 16B reads, 64 floats apart
            ulonglong2 aA = *(const ulonglong2*)&As[kk][tm * 4];
            ulonglong2 aB = *(const ulonglong2*)&As[kk][64 + tm * 4];
            float4 w = *(const float4*)&Ws[kk][tn * 4];
            unsigned long long wd0 = dup2(w.x), wd1 = dup2(w.y), wd2 = dup2(w.z), wd3 = dup2(w.w);
            unsigned long long ap[4] = { aA.x, aA.y, aB.x, aB.y };
#pragma unroll
            for (int mi = 0; mi < 4; mi++) {
                fma2(acc[mi][0], ap[mi], wd0);
                fma2(acc[mi][1], ap[mi], wd1);
                fma2(acc[mi][2], ap[mi], wd2);
                fma2(acc[mi][3], ap[mi], wd3);
            }
        }
        __syncthreads();
        a0r = a0n; a1r = a1n; wr = wn;
    }

    // epilogue: rows are (tm*4, tm*4+1), (tm*4+2, +3), (64+tm*4, +1), (64+tm*4+2, +3)
#pragma unroll
    for (int mi = 0; mi < 4; mi++) {
        const int mrow = (mi < 2) ? (tm * 4 + mi * 2) : (64 + tm * 4 + (mi - 2) * 2);
        const int r    = r0 + mrow;
        const int t_out = r >> 5;
        const int b_out = r & 31;   // even, pair stays within same t
#pragma unroll
        for (int ni = 0; ni < 4; ni++) {
            const int col = cb + tn * 4 + ni;
            const float bv = bias[col];
            float2 v = unpack2(acc[mi][ni]);
            v.x += bv; v.y += bv;
            *(float2*)(g_zx + (((size_t)(d * TT + t_out)) * G4 + col) * BB + b_out) = v;
        }
    }
}

// ---------------- kernel 2: persistent recurrent kernel ----------------
// dynamic smem layout (bytes)
static constexpr size_t OFF_W  = 0;                       // Wsm [768][48] f32      147456
static constexpr size_t OFF_H  = OFF_W  + 147456;         // Hs  [2][64][32] f32     16384
static constexpr size_t OFF_P  = OFF_H  + 16384;          // Part[256][25] f32x2     51200
static constexpr size_t OFF_Z  = OFF_P  + 51200;          // Zs  [768] f32x2          6144
static constexpr size_t OFF_C  = OFF_Z  + 6144;           // Cs  [192] f32x2          1536
static constexpr size_t OFF_PP = OFF_C  + 1536;           // peep cache 36 f32 (+pad)  192
static constexpr size_t REC_SMEM = OFF_PP + 192;          // = 222912 B

__global__ __launch_bounds__(RT, 1) void rec_kernel(
    const float* __restrict__ W0, const float* __restrict__ W1,
    const float* __restrict__ p0, const float* __restrict__ p1)
{
    extern __shared__ char smraw[];
    float*              Wsm  = (float*)(smraw + OFF_W);
    float*              Hs   = (float*)(smraw + OFF_H);
    unsigned long long* Part = (unsigned long long*)(smraw + OFF_P);
    unsigned long long* Zs   = (unsigned long long*)(smraw + OFF_Z);
    unsigned long long* Cs   = (unsigned long long*)(smraw + OFF_C);
    float*              Ps   = (float*)(smraw + OFF_PP);

    const int blk = blockIdx.x;
    const int d   = blk >> 6;
    const int u0  = (blk & 63) * 12;
    const float* __restrict__ Wh   = (d ? W1 : W0) + (size_t)DIN * G4;
    const float* __restrict__ peep = d ? p1 : p0;
    const int tid = threadIdx.x;

    // one-time: weights slice into smem  Wsm[k][c], c -> gate*H + u0 + uu
    for (int idx = tid; idx < HH * 48; idx += RT) {
        const int k = idx / 48, c = idx - k * 48;
        const int gcol = (c / 12) * HH + u0 + (c % 12);
        Wsm[idx] = Wh[(size_t)k * G4 + gcol];
    }
    if (tid < 36)  Ps[tid] = peep[(tid / 12) * HH + u0 + (tid % 12)];
    if (tid < 192) Cs[tid] = 0ULL;
    __syncthreads();

    // geometry: warp = splitK group s2; within warp: cg (8) x bg (4)
    const int s2 = tid >> 5;
    const int cg = (tid & 31) >> 2;
    const int bg = tid & 3;
    const int c0 = cg * 6;
    const int b8 = bg * 8;

    unsigned long long zxr[3];
    {   // prefetch zx for step 0
        const int t0 = d ? (TT - 1) : 0;
#pragma unroll
        for (int i = 0; i < 3; i++) {
            const int o = tid * 3 + i;
            const int c = o >> 4, bp = o & 15;
            const size_t a = (((size_t)(d * TT + t0)) * G4 + (c / 12) * HH + u0 + (c % 12)) * BB + bp * 2;
            zxr[i] = *(const unsigned long long*)(g_zx + a);
        }
    }

    for (int s = 0; s < TT; s++) {
        const int t = d ? (TT - 1 - s) : s;

        unsigned long long acc[6][4];
#pragma unroll
        for (int i = 0; i < 6; i++)
#pragma unroll
            for (int j = 0; j < 4; j++) acc[i][j] = 0ULL;

        if (s > 0) {
            const int tprev = d ? (t + 1) : (t - 1);
            const float* __restrict__ hp = g_hbuf + (size_t)(d * TT + tprev) * HH * BB;

            float4 st0 = *(const float4*)(hp + tid * 8);
            float4 st1 = *(const float4*)(hp + tid * 8 + 4);
            int buf = 0;
            for (int ch = 0; ch < 12; ch++) {
                float* hdst = Hs + buf * 2048;
                *(float4*)(hdst + tid * 8)     = st0;
                *(float4*)(hdst + tid * 8 + 4) = st1;
                __syncthreads();
                if (ch < 11) {
                    const float* hsrc = hp + (size_t)(ch + 1) * 2048;
                    st0 = *(const float4*)(hsrc + tid * 8);
                    st1 = *(const float4*)(hsrc + tid * 8 + 4);
                }
                const float* hc = hdst + s2 * 8 * 32;        // this warp's 8 k-rows
                const float* wk = Wsm + (size_t)(ch * 64 + s2 * 8) * 48;
#pragma unroll
                for (int kk = 0; kk < 8; kk++) {
                    ulonglong2 aA = *(const ulonglong2*)(hc + kk * 32 + b8);
                    ulonglong2 aB = *(const ulonglong2*)(hc + kk * 32 + b8 + 4);
                    unsigned long long ap[4] = { aA.x, aA.y, aB.x, aB.y };
                    const float* wrow = wk + kk * 48 + c0;
#pragma unroll
                    for (int cc = 0; cc < 6; cc++) {
                        const unsigned long long wd = dup2(wrow[cc]);
                        fma2(acc[cc][0], ap[0], wd);
                        fma2(acc[cc][1], ap[1], wd);
                        fma2(acc[cc][2], ap[2], wd);
                        fma2(acc[cc][3], ap[3], wd);
                    }
                }
                __syncthreads();
                buf ^= 1;
            }
        }

        // write splitK partials (row stride 25 to avoid bank conflicts)
        {
            unsigned long long* pp = Part + (size_t)tid * 25;
#pragma unroll
            for (int cc = 0; cc < 6; cc++)
#pragma unroll
                for (int j = 0; j < 4; j++) pp[cc * 4 + j] = acc[cc][j];
        }
        __syncthreads();

        // reduction: output o = c*16 + bp ; add zx here
#pragma unroll
        for (int i = 0; i < 3; i++) {
            const int o = tid * 3 + i;
            const int c = o >> 4, bp = o & 15;
            const int slot   = (c % 6) * 4 + (bp & 3);
            const int base_t = (c / 6) * 4 + (bp >> 2);
            float2 sum = unpack2(zxr[i]);
#pragma unroll
            for (int k2 = 0; k2 < 8; k2++) {
                const float2 v = unpack2(Part[(size_t)(k2 * 32 + base_t) * 25 + slot]);
                sum.x += v.x; sum.y += v.y;
            }
            Zs[o] = pack2(sum.x, sum.y);
        }
        __syncthreads();

        // elementwise LSTM update: 12 units x 16 batch-pairs = 192 tasks
        if (tid < 192) {
            const int u  = tid >> 4;
            const int bp = tid & 15;
            const float2 zi = unpack2(Zs[(0 * 12 + u) * 16 + bp]);
            const float2 zj = unpack2(Zs[(1 * 12 + u) * 16 + bp]);
            const float2 zf = unpack2(Zs[(2 * 12 + u) * 16 + bp]);
            const float2 zo = unpack2(Zs[(3 * 12 + u) * 16 + bp]);
            const float2 cp = unpack2(Cs[u * 16 + bp]);
            const float wi = Ps[u], wf = Ps[12 + u], wo = Ps[24 + u];

            const float ix = sigf(zi.x + wi * cp.x);
            const float fx = sigf(zf.x + 1.0f + wf * cp.x);
            const float cx = fx * cp.x + ix * tanhfast(zj.x);
            const float ox = sigf(zo.x + wo * cx);
            const float hx = ox * tanhfast(cx);

            const float iy = sigf(zi.y + wi * cp.y);
            const float fy = sigf(zf.y + 1.0f + wf * cp.y);
            const float cy = fy * cp.y + iy * tanhfast(zj.y);
            const float oy = sigf(zo.y + wo * cy);
            const float hy = oy * tanhfast(cy);

            Cs[u * 16 + bp] = pack2(cx, cy);
            *(unsigned long long*)(g_hbuf + ((size_t)(d * TT + t) * HH + u0 + u) * BB + bp * 2) = pack2(hx, hy);
        }

        // prefetch zx for next step (hidden behind the barrier)
        if (s + 1 < TT) {
            const int tn = d ? (TT - 2 - s) : (s + 1);
#pragma unroll
            for (int i = 0; i < 3; i++) {
                const int o = tid * 3 + i;
                const int c = o >> 4, bp = o & 15;
                const size_t a = (((size_t)(d * TT + tn)) * G4 + (c / 12) * HH + u0 + (c % 12)) * BB + bp * 2;
                zxr[i] = *(const unsigned long long*)(g_zx + a);
            }
        }

        // device-wide sense-reversing barrier
        __syncthreads();
        if (tid == 0) {
            __threadfence();
            const unsigned my = *(volatile unsigned*)&g_bar_gen;
            if (atomicAdd(&g_bar_count, 1u) == NBLK - 1) {
                atomicExch(&g_bar_count, 0u);
                __threadfence();
                atomicAdd(&g_bar_gen, 1u);
            } else {
                while (*(volatile unsigned*)&g_bar_gen == my) { }
            }
            __threadfence();
        }
        __syncthreads();
    }
}

// ---------------- kernel 3: transpose to [b][t][2H] ----------------
__global__ __launch_bounds__(256) void out_kernel(float* __restrict__ out)
{
    const int d  = blockIdx.z;
    const int t  = blockIdx.y;
    const int n0 = blockIdx.x * 32;
    const int tid = threadIdx.x;

    __shared__ float tile[32][33];

    const float* __restrict__ src = g_hbuf + ((size_t)(d * TT + t) * HH + n0) * BB;
#pragma unroll
    for (int q = 0; q < 4; q++) {
        const int lin = tid + q * 256;
        tile[lin >> 5][lin & 31] = src[lin];
    }
    __syncthreads();

    const int b  = tid >> 3;
    const int nq = (tid & 7) * 4;
    float4 v;
    v.x = tile[nq + 0][b];
    v.y = tile[nq + 1][b];
    v.z = tile[nq + 2][b];
    v.w = tile[nq + 3][b];
    *(float4*)(out + ((size_t)b * TT + t) * (2 * HH) + d * HH + n0 + nq) = v;
}

// ---------------- launch ----------------
extern "C" void kernel_launch(void* const* d_in, const int* in_sizes, int n_in,
                              void* d_out, int out_size)
{
    (void)in_sizes; (void)n_in; (void)out_size;
    const float* x  = (const float*)d_in[0];
    const float* Wf = (const float*)d_in[1];
    const float* bf = (const float*)d_in[2];
    const float* pf = (const float*)d_in[3];
    const float* Wb = (const float*)d_in[4];
    const float* bb = (const float*)d_in[5];
    const float* pb = (const float*)d_in[6];
    float* out = (float*)d_out;

    static bool attr_done = false;
    if (!attr_done) {
        cudaFuncSetAttribute(rec_kernel, cudaFuncAttributeMaxDynamicSharedMemorySize, (int)REC_SMEM);
        attr_done = true;
    }

    zx_kernel<<<dim3(48, 256, 2), 256>>>(x, Wf, Wb, bf, bb);
    rec_kernel<<<NBLK, RT, REC_SMEM>>>(Wf, Wb, pf, pb);
    out_kernel<<<dim3(24, TT, 2), 256>>>(out);
}